// round 17
// baseline (speedup 1.0000x reference)
#include <cuda_runtime.h>
#include <cstdint>

// ---------------- problem constants ----------------
#define ROWG   64
#define IN_DIM 1024
#define OUT_D  1024
#define BATCH  512

// ---------------- tiling ----------------
#define BM 128
#define BN 256
#define BK 128
#define KT (IN_DIM / BK)   // 8 k-tiles

// ---------------- smem layout (bytes) ----------------
#define A_ROW_B 256                 // 128 fp16 = 16 chunks, XOR swizzle on low 3 bits
#define A_STG   (BM * A_ROW_B)      // 32768
#define B_ROW_B 528                 // 256 fp16 (512B) + 16B pad
#define B_STG   (BK * B_ROW_B)      // 67584
#define STAGES  2
#define SMEM_TOTAL (STAGES * (A_STG + B_STG))  // 200704 (196KB, 1 CTA/SM)

__device__ __forceinline__ uint32_t packh(float hi, float lo) {
    uint32_t w;
    asm("cvt.rn.f16x2.f32 %0, %1, %2;" : "=r"(w) : "f"(hi), "f"(lo));
    return w;
}

// rotated swizzle: bijective on 0..7, adjacent rows -> opposite 4-chunk halves
__device__ __forceinline__ int swz(int row) {
    return ((row & 1) << 2) | ((row & 6) >> 1);
}

#define LDSM4(R, ADDR) \
    asm volatile("ldmatrix.sync.aligned.m8n8.x4.shared.b16 {%0,%1,%2,%3}, [%4];" \
        : "=r"((R)[0]), "=r"((R)[1]), "=r"((R)[2]), "=r"((R)[3]) : "r"(ADDR))

#define LDSM4T(R, ADDR) \
    asm volatile("ldmatrix.sync.aligned.m8n8.x4.trans.shared.b16 {%0,%1,%2,%3}, [%4];" \
        : "=r"((R)[0]), "=r"((R)[1]), "=r"((R)[2]), "=r"((R)[3]) : "r"(ADDR))

#define MMA16(C, A, B0, B1) \
    asm volatile("mma.sync.aligned.m16n8k16.row.col.f32.f16.f16.f32 " \
        "{%0,%1,%2,%3}, {%4,%5,%6,%7}, {%8,%9}, {%0,%1,%2,%3};" \
        : "+f"((C)[0]), "+f"((C)[1]), "+f"((C)[2]), "+f"((C)[3]) \
        : "r"((A)[0]), "r"((A)[1]), "r"((A)[2]), "r"((A)[3]), "r"(B0), "r"(B1))

__global__ __launch_bounds__(256, 1)
void gmlp_f16k128(const float* __restrict__ x,
                  const float* __restrict__ W,
                  const float* __restrict__ bias,
                  float* __restrict__ out)
{
    extern __shared__ __align__(16) char smem[];
    const uint32_t sbA = (uint32_t)__cvta_generic_to_shared(smem);
    const uint32_t sbB = sbA + STAGES * A_STG;

    const int r  = blockIdx.z;
    const int n0 = blockIdx.x * BN;
    const int m0 = blockIdx.y * BM;

    const int tid  = threadIdx.x;
    const int wid  = tid >> 5;
    const int lane = tid & 31;
    const int wm   = wid & 1;            // 2 m-warps of 64 rows
    const int wn   = wid >> 1;           // 4 n-warps of 64 cols
    const int g    = lane >> 2;
    const int tg   = lane & 3;

    // ---- loader: A — 8 lanes per 128B fp32 chunk-pair, full-line LDGs ----
    const int arow = tid >> 3;            // 0..31, rows arow + 32p
    const int achk = tid & 7;             // 16B unit within 128B gmem segment
    const float* xA = x + (size_t)(m0 + arow) * (ROWG * IN_DIM)
                        + (size_t)r * IN_DIM + achk * 4;
    const size_t A_P = (size_t)32 * (ROWG * IN_DIM);     // +32 batch rows
    const int e_ar = swz(arow & 7);
    // fp16 dest chunk (16 per row): c = (H&1)*4 + (achk>>1), low3 swizzled; bit3 = H>>1
    const uint32_t saA_base = sbA + arow * A_ROW_B + (achk & 1) * 8;
    uint32_t saA[4];
    #pragma unroll
    for (int h = 0; h < 4; h++)
        saA[h] = saA_base + ((((h & 1) * 4 + (achk >> 1)) ^ e_ar) * 16) + (h >> 1) * 128;

    // ---- loader: B — 16 lanes per 256B segment, 2 rows per warp-instr ----
    const int bq_row = tid >> 4;          // 0..15
    const int bq_col = tid & 15;
    const float* xB = W + (size_t)r * IN_DIM * OUT_D
                        + (size_t)bq_row * OUT_D + n0 + bq_col * 4;
    const uint32_t saB = sbB + bq_row * B_ROW_B + bq_col * 8;

    // ---- consumer ldmatrix base addresses ----
    const int hb = lane >> 4;
    const int e_ln = swz(lane & 7);
    const uint32_t aBase = sbA + (wm * 64 + (lane & 15)) * A_ROW_B;
    uint32_t aoff[8];
    #pragma unroll
    for (int ks = 0; ks < 8; ks++)
        aoff[ks] = (uint32_t)(((2 * ks + hb) ^ e_ln) * 16);   // XOR only touches low 3 bits
    const uint32_t bBase = sbB + ((lane & 7) + ((lane >> 3) & 1) * 8) * B_ROW_B
                               + (wn * 8 + hb) * 16;

    float acc[4][8][4];
    #pragma unroll
    for (int mt = 0; mt < 4; mt++)
        #pragma unroll
        for (int nt = 0; nt < 8; nt++)
            #pragma unroll
            for (int i = 0; i < 4; i++)
                acc[mt][nt][i] = 0.0f;

    float stA[16], stB[32];

// load quarter H (32 k-cols) of tile T into staging regs — all instrs full-line
#define LOAD_H(T, H) do {                                                    \
    _Pragma("unroll")                                                        \
    for (int p_ = 0; p_ < 4; p_++) {                                         \
        float4 v_ = *(const float4*)(xA + (size_t)(T) * BK + (H) * 32 + p_ * A_P); \
        stA[p_*4+0]=v_.x; stA[p_*4+1]=v_.y; stA[p_*4+2]=v_.z; stA[p_*4+3]=v_.w; \
    }                                                                        \
    _Pragma("unroll")                                                        \
    for (int q_ = 0; q_ < 8; q_++) {                                         \
        float4 u_ = *(const float4*)(xB                                      \
            + (size_t)((T) * BK + (H) * 32 + 16 * (q_ & 1)) * OUT_D          \
            + (q_ >> 1) * 64);                                               \
        stB[q_*4+0]=u_.x; stB[q_*4+1]=u_.y; stB[q_*4+2]=u_.z; stB[q_*4+3]=u_.w; \
    }                                                                        \
} while (0)

// store staged quarter H into stage BUF
#define STS_H(BUF, H) do {                                                   \
    const uint32_t sa_ = saA[H] + (BUF) * A_STG;                             \
    _Pragma("unroll")                                                        \
    for (int p_ = 0; p_ < 4; p_++) {                                         \
        asm volatile("st.shared.v2.b32 [%0], {%1,%2};"                       \
            :: "r"(sa_ + p_ * (32 * A_ROW_B)),                               \
               "r"(packh(stA[p_*4+1], stA[p_*4+0])),                         \
               "r"(packh(stA[p_*4+3], stA[p_*4+2])));                        \
    }                                                                        \
    const uint32_t sb_ = saB + (BUF) * B_STG + (H) * (32 * B_ROW_B);         \
    _Pragma("unroll")                                                        \
    for (int q_ = 0; q_ < 8; q_++) {                                         \
        asm volatile("st.shared.v2.b32 [%0], {%1,%2};"                       \
            :: "r"(sb_ + (q_ & 1) * (16 * B_ROW_B) + (q_ >> 1) * 128),       \
               "r"(packh(stB[q_*4+1], stB[q_*4+0])),                         \
               "r"(packh(stB[q_*4+3], stB[q_*4+2])));                        \
    }                                                                        \
} while (0)

// compute one k16 group KS (compile-time) of stage BUF
#define COMPUTE_G(BUF, KS) do {                                              \
    uint32_t a_[4][4];                                                       \
    _Pragma("unroll")                                                        \
    for (int mt_ = 0; mt_ < 4; mt_++)                                        \
        LDSM4(a_[mt_], aBase + (BUF) * A_STG + mt_ * (16 * A_ROW_B) + aoff[KS]); \
    _Pragma("unroll")                                                        \
    for (int p_ = 0; p_ < 4; p_++) {                                         \
        uint32_t bb_[4];                                                     \
        LDSM4T(bb_, bBase + (BUF) * B_STG + (KS) * (16 * B_ROW_B) + p_ * 32); \
        _Pragma("unroll")                                                    \
        for (int mt_ = 0; mt_ < 4; mt_++) {                                  \
            MMA16(acc[mt_][2 * p_],     a_[mt_], bb_[0], bb_[1]);            \
            MMA16(acc[mt_][2 * p_ + 1], a_[mt_], bb_[2], bb_[3]);            \
        }                                                                    \
    }                                                                        \
} while (0)

    // ---- prologue: tile0 fully staged; tile1 quarter0 in regs ----
    LOAD_H(0, 0);  STS_H(0, 0);
    LOAD_H(0, 1);  STS_H(0, 1);
    LOAD_H(0, 2);  STS_H(0, 2);
    LOAD_H(0, 3);  STS_H(0, 3);
    LOAD_H(1, 0);
    __syncthreads();

    // ---- main loop: 2-stage ring, quarter-phase staging, 8 barriers ----
    #pragma unroll 1
    for (int kt = 0; kt < KT; kt++) {
        const int s_cmp = kt & 1;
        const int s_nxt = s_cmp ^ 1;
        if (kt + 1 < KT) { STS_H(s_nxt, 0); LOAD_H(kt + 1, 1); }
        COMPUTE_G(s_cmp, 0);
        COMPUTE_G(s_cmp, 1);
        if (kt + 1 < KT) { STS_H(s_nxt, 1); LOAD_H(kt + 1, 2); }
        COMPUTE_G(s_cmp, 2);
        COMPUTE_G(s_cmp, 3);
        if (kt + 1 < KT) { STS_H(s_nxt, 2); LOAD_H(kt + 1, 3); }
        COMPUTE_G(s_cmp, 4);
        COMPUTE_G(s_cmp, 5);
        if (kt + 1 < KT) { STS_H(s_nxt, 3); }
        if (kt + 2 < KT) { LOAD_H(kt + 2, 0); }
        COMPUTE_G(s_cmp, 6);
        COMPUTE_G(s_cmp, 7);
        __syncthreads();
    }

    // ---- epilogue: add bias, store ----
    const float* bp = bias + (size_t)r * OUT_D + n0;
    #pragma unroll
    for (int mt = 0; mt < 4; mt++) {
        #pragma unroll
        for (int nt = 0; nt < 8; nt++) {
            int row0 = wm * 64 + mt * 16 + g;
            int col  = wn * 64 + nt * 8 + tg * 2;
            float b0 = bp[col];
            float b1 = bp[col + 1];
            float2 v0 = make_float2(acc[mt][nt][0] + b0, acc[mt][nt][1] + b1);
            float2 v1 = make_float2(acc[mt][nt][2] + b0, acc[mt][nt][3] + b1);
            size_t o0 = ((size_t)(m0 + row0)     * ROWG + r) * OUT_D + n0 + col;
            size_t o1 = ((size_t)(m0 + row0 + 8) * ROWG + r) * OUT_D + n0 + col;
            *reinterpret_cast<float2*>(out + o0) = v0;
            *reinterpret_cast<float2*>(out + o1) = v1;
        }
    }
}

extern "C" void kernel_launch(void* const* d_in, const int* in_sizes, int n_in,
                              void* d_out, int out_size) {
    const float* x    = (const float*)d_in[0];  // (512, 64, 1024)
    const float* W    = (const float*)d_in[1];  // (64, 1024, 1024)
    const float* bias = (const float*)d_in[2];  // (64, 1024)
    float* out = (float*)d_out;                 // (512, 64, 1024)

    cudaFuncSetAttribute(gmlp_f16k128,
                         cudaFuncAttributeMaxDynamicSharedMemorySize, SMEM_TOTAL);
    dim3 grid(OUT_D / BN, BATCH / BM, ROWG);    // (4, 4, 64)
    gmlp_f16k128<<<grid, 256, SMEM_TOTAL>>>(x, W, bias, out);
}